// round 10
// baseline (speedup 1.0000x reference)
#include <cuda_runtime.h>
#include <cuda_bf16.h>
#include <cstdint>

#define N_NODES 100000
#define N_EDGES 600000
#define HID 128
#define OUT 24

// ---------------- scratch ----------------
__device__ float g_h   [(size_t)N_NODES * HID];
__device__ float g_agg [(size_t)N_NODES * HID];
__device__ float g_hid [(size_t)N_NODES * HID];
__device__ float g_eas [(size_t)N_EDGES * 32];
__device__ int   g_srcs[N_EDGES];
__device__ int   g_dsts[N_EDGES];
__device__ int   g_deg [N_NODES];
__device__ int   g_off [N_NODES + 1];
__device__ int   g_cur [N_NODES];
__device__ int   g_perm[N_EDGES];

// ---------------- helpers ----------------
__device__ __forceinline__ unsigned long long pk2(float lo, float hi) {
    unsigned long long r;
    asm("mov.b64 %0, {%1, %2};" : "=l"(r) : "f"(lo), "f"(hi));
    return r;
}
__device__ __forceinline__ void fma2(unsigned long long& d,
                                     unsigned long long a, unsigned long long b) {
    asm("fma.rn.f32x2 %0, %1, %2, %0;" : "+l"(d) : "l"(a), "l"(b));
}
__device__ __forceinline__ float2 upk(unsigned long long v) {
    float2 f;
    asm("mov.b64 {%0, %1}, %2;" : "=f"(f.x), "=f"(f.y) : "l"(v));
    return f;
}
__device__ __forceinline__ uint32_t f2tf32(float f) {
    uint32_t u;
    asm("cvt.rna.tf32.f32 %0, %1;" : "=r"(u) : "f"(f));
    return u;
}
__device__ __forceinline__ void red_add_v4(float* addr, float4 v) {
    asm volatile("red.global.add.v4.f32 [%0], {%1, %2, %3, %4};"
                 :: "l"(addr), "f"(v.x), "f"(v.y), "f"(v.z), "f"(v.w)
                 : "memory");
}
__device__ __forceinline__ void mma_tf32(float* c, const uint32_t* a,
                                         uint32_t b0, uint32_t b1) {
    asm volatile(
        "mma.sync.aligned.m16n8k8.row.col.f32.tf32.tf32.f32 "
        "{%0,%1,%2,%3}, {%4,%5,%6,%7}, {%8,%9}, {%0,%1,%2,%3};"
        : "+f"(c[0]), "+f"(c[1]), "+f"(c[2]), "+f"(c[3])
        : "r"(a[0]), "r"(a[1]), "r"(a[2]), "r"(a[3]), "r"(b0), "r"(b1));
}

// ---------------- tf32 tensor-core GEMM (exact R7) -------------------------
#define BM 128
#define BN 128
#define BK 16
#define APAD 136

template<bool RELU>
__global__ __launch_bounds__(256)
void tgemm_kernel(const float* __restrict__ A, int lda,
                  const float* __restrict__ W, int ldw,
                  const float* __restrict__ bias,
                  float* __restrict__ C, int ldc,
                  int M, int K)
{
    __shared__ uint32_t As[BK][APAD];
    __shared__ uint32_t Ws[BK][APAD];

    const int tid  = threadIdx.x;
    const int m0   = blockIdx.y * BM;
    const int warp = tid >> 5;
    const int lane = tid & 31;
    const int g    = lane >> 2;
    const int tig  = lane & 3;
    const int wm   = (warp & 3) * 32;
    const int wn   = (warp >> 2) * 64;

    float acc[2][8][4];
    #pragma unroll
    for (int i = 0; i < 2; i++)
        #pragma unroll
        for (int j = 0; j < 8; j++)
            #pragma unroll
            for (int q = 0; q < 4; q++) acc[i][j][q] = 0.f;

    for (int k0 = 0; k0 < K; k0 += BK) {
        #pragma unroll
        for (int p = 0; p < 2; p++) {
            int idx = tid + p * 256;
            int m   = idx >> 2;
            int k4  = (idx & 3) << 2;
            float4 v = make_float4(0.f, 0.f, 0.f, 0.f);
            int gm = m0 + m;
            if (gm < M)
                v = *reinterpret_cast<const float4*>(A + (size_t)gm * lda + k0 + k4);
            As[k4 + 0][m] = f2tf32(v.x);
            As[k4 + 1][m] = f2tf32(v.y);
            As[k4 + 2][m] = f2tf32(v.z);
            As[k4 + 3][m] = f2tf32(v.w);
        }
        #pragma unroll
        for (int p = 0; p < 2; p++) {
            int idx = tid + p * 256;
            int k   = idx >> 5;
            int n4  = (idx & 31) << 2;
            float4 v = *reinterpret_cast<const float4*>(W + (size_t)(k0 + k) * ldw + n4);
            Ws[k][n4 + 0] = f2tf32(v.x);
            Ws[k][n4 + 1] = f2tf32(v.y);
            Ws[k][n4 + 2] = f2tf32(v.z);
            Ws[k][n4 + 3] = f2tf32(v.w);
        }
        __syncthreads();

        #pragma unroll
        for (int kk = 0; kk < BK; kk += 8) {
            uint32_t a[2][4];
            #pragma unroll
            for (int mf = 0; mf < 2; mf++) {
                a[mf][0] = As[kk + tig    ][wm + mf * 16 + g];
                a[mf][1] = As[kk + tig    ][wm + mf * 16 + g + 8];
                a[mf][2] = As[kk + tig + 4][wm + mf * 16 + g];
                a[mf][3] = As[kk + tig + 4][wm + mf * 16 + g + 8];
            }
            #pragma unroll
            for (int nf = 0; nf < 8; nf++) {
                uint32_t b0 = Ws[kk + tig    ][wn + nf * 8 + g];
                uint32_t b1 = Ws[kk + tig + 4][wn + nf * 8 + g];
                #pragma unroll
                for (int mf = 0; mf < 2; mf++)
                    mma_tf32(acc[mf][nf], a[mf], b0, b1);
            }
        }
        __syncthreads();
    }

    #pragma unroll
    for (int mf = 0; mf < 2; mf++) {
        int r0 = m0 + wm + mf * 16 + g;
        #pragma unroll
        for (int nf = 0; nf < 8; nf++) {
            int col = wn + nf * 8 + 2 * tig;
            float bv0 = bias ? bias[col]     : 0.f;
            float bv1 = bias ? bias[col + 1] : 0.f;
            float c0 = acc[mf][nf][0] + bv0, c1 = acc[mf][nf][1] + bv1;
            float c2 = acc[mf][nf][2] + bv0, c3 = acc[mf][nf][3] + bv1;
            if (RELU) {
                c0 = fmaxf(c0, 0.f); c1 = fmaxf(c1, 0.f);
                c2 = fmaxf(c2, 0.f); c3 = fmaxf(c3, 0.f);
            }
            if (r0 < M)
                *reinterpret_cast<float2*>(C + (size_t)r0 * ldc + col) = make_float2(c0, c1);
            if (r0 + 8 < M)
                *reinterpret_cast<float2*>(C + (size_t)(r0 + 8) * ldc + col) = make_float2(c2, c3);
        }
    }
}

// ---------------- utility kernels ----------------
__global__ void copy_kernel(float4* __restrict__ dst, const float4* __restrict__ src, int n4)
{
    int i = blockIdx.x * blockDim.x + threadIdx.x;
    if (i < n4) dst[i] = src[i];
}

__global__ void zero_int_kernel(int* __restrict__ p, int n)
{
    int i = blockIdx.x * blockDim.x + threadIdx.x;
    if (i < n) p[i] = 0;
}

__global__ void hist_kernel(const int* __restrict__ dst, int* __restrict__ deg, int E)
{
    int e = blockIdx.x * blockDim.x + threadIdx.x;
    if (e < E) atomicAdd(&deg[dst[e]], 1);
}

__global__ __launch_bounds__(1024)
void scan_kernel(const int* __restrict__ deg, int* __restrict__ off,
                 int* __restrict__ cur, int n)
{
    __shared__ int wsum[32];
    __shared__ int carry_s;
    const int tid = threadIdx.x;
    const int lane = tid & 31, wid = tid >> 5;
    if (tid == 0) { carry_s = 0; off[0] = 0; }
    __syncthreads();
    for (int base = 0; base < n; base += 1024) {
        int i = base + tid;
        int v = (i < n) ? deg[i] : 0;
        int x = v;
        #pragma unroll
        for (int o = 1; o < 32; o <<= 1) {
            int y = __shfl_up_sync(0xffffffff, x, o);
            if (lane >= o) x += y;
        }
        if (lane == 31) wsum[wid] = x;
        __syncthreads();
        if (wid == 0) {
            int s = wsum[lane];
            #pragma unroll
            for (int o = 1; o < 32; o <<= 1) {
                int y = __shfl_up_sync(0xffffffff, s, o);
                if (lane >= o) s += y;
            }
            wsum[lane] = s;
        }
        __syncthreads();
        int warp_off = (wid == 0) ? 0 : wsum[wid - 1];
        int incl = carry_s + warp_off + x;
        if (i < n) {
            off[i + 1] = incl;
            cur[i] = incl - v;
        }
        __syncthreads();
        if (tid == 0) carry_s += wsum[31];
        __syncthreads();
    }
}

__global__ void fill_kernel(const int* __restrict__ dst, int* __restrict__ cur,
                            int* __restrict__ perm, int E)
{
    int e = blockIdx.x * blockDim.x + threadIdx.x;
    if (e < E) {
        int p = atomicAdd(&cur[dst[e]], 1);
        perm[p] = e;
    }
}

__global__ __launch_bounds__(128)
void permute_kernel(const int* __restrict__ perm,
                    const int* __restrict__ src,
                    const int* __restrict__ dst,
                    const float* __restrict__ ea,
                    float* __restrict__ eas,
                    int* __restrict__ srcs,
                    int* __restrict__ dsts,
                    int E)
{
    __shared__ int perm_s[32];
    const int base = blockIdx.x * 32;
    const int ne = min(32, E - base);
    if (ne <= 0) return;
    if (threadIdx.x < ne) {
        int p = perm[base + threadIdx.x];
        perm_s[threadIdx.x] = p;
        srcs[base + threadIdx.x] = src[p];
        dsts[base + threadIdx.x] = dst[p];
    }
    __syncthreads();
    for (int idx = threadIdx.x; idx < ne * 8; idx += 128) {
        int e = idx >> 3;
        int q = idx & 7;
        float4 v = *reinterpret_cast<const float4*>(ea + (size_t)perm_s[e] * 32 + q * 4);
        *reinterpret_cast<float4*>(eas + (size_t)(base + e) * 32 + q * 4) = v;
    }
}

// ---------------- TC edge scatter on sorted edges + run-merged v4 flush ----
// Phase 1: e_emb[64x128] = ea@ew + eb via mma.sync -> m_s (row layout SMEM)
// Phase 2: warp walks 8 consecutive dst-sorted edges, lane owns a quad;
//          accumulates relu(m+h[src]) in regs, one red.add.v4 per dst-run.
#define SE 64
#define MROW 132

__global__ __launch_bounds__(256)
void edge_scatter_tc(const float* __restrict__ h,
                     const int* __restrict__ srcs,
                     const int* __restrict__ dsts,
                     const float* __restrict__ eas,
                     const float* __restrict__ ew,
                     const float* __restrict__ eb,
                     float* __restrict__ agg,
                     int E)
{
    __shared__ char pool[SE * MROW * 4 + 2 * SE * 4];
    uint32_t (*ea_s)[SE + 8] = reinterpret_cast<uint32_t(*)[SE + 8]>(pool);
    uint32_t (*ew_s)[136]    = reinterpret_cast<uint32_t(*)[136]>(pool + 9216);
    float    (*m_s)[MROW]    = reinterpret_cast<float(*)[MROW]>(pool);
    int* src_s = reinterpret_cast<int*>(pool + SE * MROW * 4);
    int* dst_s = src_s + SE;

    const int tid  = threadIdx.x;
    const int warp = tid >> 5;
    const int lane = tid & 31;
    const int g    = lane >> 2;
    const int tig  = lane & 3;
    const int wn   = warp * 16;

    const int base = blockIdx.x * SE;
    const int ne = min(SE, E - base);
    if (ne <= 0) return;

    for (int idx = tid; idx < 32 * HID; idx += 256)
        ew_s[idx >> 7][idx & 127] = f2tf32(ew[idx]);
    for (int idx = tid; idx < SE * 32; idx += 256) {
        int e = idx >> 5, k = idx & 31;
        float v = (e < ne) ? eas[(size_t)(base + e) * 32 + k] : 0.f;
        ea_s[k][e] = f2tf32(v);
    }
    if (tid < ne) {
        src_s[tid] = srcs[base + tid];
        dst_s[tid] = dsts[base + tid];
    }
    __syncthreads();

    float acc[4][2][4];
    #pragma unroll
    for (int mf = 0; mf < 4; mf++)
        #pragma unroll
        for (int nf = 0; nf < 2; nf++)
            #pragma unroll
            for (int q = 0; q < 4; q++) acc[mf][nf][q] = 0.f;

    #pragma unroll
    for (int kk = 0; kk < 32; kk += 8) {
        uint32_t a[4][4];
        #pragma unroll
        for (int mf = 0; mf < 4; mf++) {
            a[mf][0] = ea_s[kk + tig    ][mf * 16 + g];
            a[mf][1] = ea_s[kk + tig    ][mf * 16 + g + 8];
            a[mf][2] = ea_s[kk + tig + 4][mf * 16 + g];
            a[mf][3] = ea_s[kk + tig + 4][mf * 16 + g + 8];
        }
        #pragma unroll
        for (int nf = 0; nf < 2; nf++) {
            uint32_t b0 = ew_s[kk + tig    ][wn + nf * 8 + g];
            uint32_t b1 = ew_s[kk + tig + 4][wn + nf * 8 + g];
            #pragma unroll
            for (int mf = 0; mf < 4; mf++)
                mma_tf32(acc[mf][nf], a[mf], b0, b1);
        }
    }

    const int col0 = wn + 2 * tig;
    const float2 eb0 = *reinterpret_cast<const float2*>(eb + col0);
    const float2 eb1 = *reinterpret_cast<const float2*>(eb + col0 + 8);
    __syncthreads();

    #pragma unroll
    for (int mf = 0; mf < 4; mf++) {
        int r = mf * 16 + g;
        *reinterpret_cast<float2*>(&m_s[r][col0]) =
            make_float2(acc[mf][0][0] + eb0.x, acc[mf][0][1] + eb0.y);
        *reinterpret_cast<float2*>(&m_s[r][col0 + 8]) =
            make_float2(acc[mf][1][0] + eb1.x, acc[mf][1][1] + eb1.y);
        *reinterpret_cast<float2*>(&m_s[r + 8][col0]) =
            make_float2(acc[mf][0][2] + eb0.x, acc[mf][0][3] + eb0.y);
        *reinterpret_cast<float2*>(&m_s[r + 8][col0 + 8]) =
            make_float2(acc[mf][1][2] + eb1.x, acc[mf][1][3] + eb1.y);
    }
    __syncthreads();

    // phase 2: warp walks 8 consecutive sorted edges; run-merged v4 flush
    const int w0 = warp * 8;
    if (w0 < ne) {
        float4 acc4 = make_float4(0.f, 0.f, 0.f, 0.f);
        int cur = dst_s[w0];
        #pragma unroll
        for (int i = 0; i < 8; i++) {
            int e = w0 + i;
            if (e >= ne) break;
            int dd = dst_s[e];              // warp-uniform
            if (dd != cur) {
                red_add_v4(agg + (size_t)cur * HID + lane * 4, acc4);
                acc4 = make_float4(0.f, 0.f, 0.f, 0.f);
                cur = dd;
            }
            float4 m  = *reinterpret_cast<const float4*>(&m_s[e][lane * 4]);
            float4 hv = *reinterpret_cast<const float4*>(h + (size_t)src_s[e] * HID + lane * 4);
            acc4.x += fmaxf(m.x + hv.x, 0.f);
            acc4.y += fmaxf(m.y + hv.y, 0.f);
            acc4.z += fmaxf(m.z + hv.z, 0.f);
            acc4.w += fmaxf(m.w + hv.w, 0.f);
        }
        red_add_v4(agg + (size_t)cur * HID + lane * 4, acc4);
    }
}

// ---------------- TC classifier (exact R9) ---------------------------------
#define HS_OFF   0
#define HS_ROW   132
#define EA_OFF   33792
#define W1C_OFF  (EA_OFF + 9216)
#define W2T_OFF  33792
#define W2T_ROW  132
#define IDX_OFF  60416
#define CLS_SMEM 60928

__global__ __launch_bounds__(256)
void cls_tc_kernel(const float* __restrict__ P,
                   const float* __restrict__ Q,
                   const int* __restrict__ src,
                   const int* __restrict__ dst,
                   const float* __restrict__ ea,
                   const float* __restrict__ w1c,
                   const float* __restrict__ b1,
                   const float* __restrict__ w2,
                   const float* __restrict__ b2,
                   float* __restrict__ out,
                   int E)
{
    extern __shared__ char smem_raw[];
    float    (*hid_s)[HS_ROW] = reinterpret_cast<float(*)[HS_ROW]>(smem_raw + HS_OFF);
    uint32_t (*ea_s)[SE + 8]  = reinterpret_cast<uint32_t(*)[SE + 8]>(smem_raw + EA_OFF);
    uint32_t (*w1c_s)[136]    = reinterpret_cast<uint32_t(*)[136]>(smem_raw + W1C_OFF);
    float    (*w2t)[W2T_ROW]  = reinterpret_cast<float(*)[W2T_ROW]>(smem_raw + W2T_OFF);
    int* src_s = reinterpret_cast<int*>(smem_raw + IDX_OFF);
    int* dst_s = src_s + SE;

    const int tid  = threadIdx.x;
    const int warp = tid >> 5;
    const int lane = tid & 31;
    const int g    = lane >> 2;
    const int tig  = lane & 3;
    const int wn   = warp * 16;

    const int base = blockIdx.x * SE;
    const int ne = min(SE, E - base);
    if (ne <= 0) return;

    for (int idx = tid; idx < 32 * HID; idx += 256)
        w1c_s[idx >> 7][idx & 127] = f2tf32(w1c[idx]);
    for (int idx = tid; idx < SE * 32; idx += 256) {
        int e = idx >> 5, k = idx & 31;
        float v = (e < ne) ? ea[(size_t)(base + e) * 32 + k] : 0.f;
        ea_s[k][e] = f2tf32(v);
    }
    if (tid < ne) {
        src_s[tid] = src[base + tid];
        dst_s[tid] = dst[base + tid];
    }
    __syncthreads();

    float acc[4][2][4];
    #pragma unroll
    for (int mf = 0; mf < 4; mf++)
        #pragma unroll
        for (int nf = 0; nf < 2; nf++)
            #pragma unroll
            for (int q = 0; q < 4; q++) acc[mf][nf][q] = 0.f;

    #pragma unroll
    for (int kk = 0; kk < 32; kk += 8) {
        uint32_t a[4][4];
        #pragma unroll
        for (int mf = 0; mf < 4; mf++) {
            a[mf][0] = ea_s[kk + tig    ][mf * 16 + g];
            a[mf][1] = ea_s[kk + tig    ][mf * 16 + g + 8];
            a[mf][2] = ea_s[kk + tig + 4][mf * 16 + g];
            a[mf][3] = ea_s[kk + tig + 4][mf * 16 + g + 8];
        }
        #pragma unroll
        for (int nf = 0; nf < 2; nf++) {
            uint32_t b0 = w1c_s[kk + tig    ][wn + nf * 8 + g];
            uint32_t b1 = w1c_s[kk + tig + 4][wn + nf * 8 + g];
            #pragma unroll
            for (int mf = 0; mf < 4; mf++)
                mma_tf32(acc[mf][nf], a[mf], b0, b1);
        }
    }

    const int col0 = wn + 2 * tig;
    const float2 bb0 = *reinterpret_cast<const float2*>(b1 + col0);
    const float2 bb1 = *reinterpret_cast<const float2*>(b1 + col0 + 8);

    #pragma unroll
    for (int mf = 0; mf < 4; mf++) {
        int r = mf * 16 + g;
        *reinterpret_cast<float2*>(&hid_s[r][col0]) =
            make_float2(acc[mf][0][0] + bb0.x, acc[mf][0][1] + bb0.y);
        *reinterpret_cast<float2*>(&hid_s[r][col0 + 8]) =
            make_float2(acc[mf][1][0] + bb1.x, acc[mf][1][1] + bb1.y);
        *reinterpret_cast<float2*>(&hid_s[r + 8][col0]) =
            make_float2(acc[mf][0][2] + bb0.x, acc[mf][0][3] + bb0.y);
        *reinterpret_cast<float2*>(&hid_s[r + 8][col0 + 8]) =
            make_float2(acc[mf][1][2] + bb1.x, acc[mf][1][3] + bb1.y);
    }
    __syncthreads();

    #pragma unroll
    for (int it = 0; it < SE / 8; it++) {
        int e = it * 8 + warp;
        if (e < ne) {
            int s = src_s[e], dd = dst_s[e];
            float4 hv = *reinterpret_cast<const float4*>(&hid_s[e][lane * 4]);
            float4 pv = *reinterpret_cast<const float4*>(P + (size_t)s * HID + lane * 4);
            float4 qv = *reinterpret_cast<const float4*>(Q + (size_t)dd * HID + lane * 4);
            hv.x = fmaxf(hv.x + pv.x + qv.x, 0.f);
            hv.y = fmaxf(hv.y + pv.y + qv.y, 0.f);
            hv.z = fmaxf(hv.z + pv.z + qv.z, 0.f);
            hv.w = fmaxf(hv.w + pv.w + qv.w, 0.f);
            *reinterpret_cast<float4*>(&hid_s[e][lane * 4]) = hv;
        }
    }
    __syncthreads();

    for (int idx = tid; idx < HID * OUT; idx += 256) {
        float v = w2[idx];
        w2t[idx % OUT][idx / OUT] = v;
    }
    __syncthreads();

    const int oq = tid & 7;
    const int eq = tid >> 3;
    const int o0 = oq * 3;
    const int e0 = eq * 2;

    unsigned long long acc2[2][3];
    #pragma unroll
    for (int i = 0; i < 2; i++)
        #pragma unroll
        for (int j = 0; j < 3; j++) acc2[i][j] = 0ull;

    #pragma unroll 4
    for (int dch = 0; dch < HID; dch += 4) {
        unsigned long long h2[2][2], w2r[3][2];
        #pragma unroll
        for (int i = 0; i < 2; i++) {
            const unsigned long long* hp =
                reinterpret_cast<const unsigned long long*>(&hid_s[e0 + i][dch]);
            h2[i][0] = hp[0]; h2[i][1] = hp[1];
        }
        #pragma unroll
        for (int j = 0; j < 3; j++) {
            const unsigned long long* wp =
                reinterpret_cast<const unsigned long long*>(&w2t[o0 + j][dch]);
            w2r[j][0] = wp[0]; w2r[j][1] = wp[1];
        }
        #pragma unroll
        for (int i = 0; i < 2; i++)
            #pragma unroll
            for (int j = 0; j < 3; j++) {
                fma2(acc2[i][j], h2[i][0], w2r[j][0]);
                fma2(acc2[i][j], h2[i][1], w2r[j][1]);
            }
    }

    #pragma unroll
    for (int i = 0; i < 2; i++) {
        int e = e0 + i;
        if (e >= ne) continue;
        #pragma unroll
        for (int j = 0; j < 3; j++) {
            float2 s = upk(acc2[i][j]);
            out[(size_t)(base + e) * OUT + o0 + j] = s.x + s.y + b2[o0 + j];
        }
    }
}

// ---------------- host ----------------
extern "C" void kernel_launch(void* const* d_in, const int* in_sizes, int n_in,
                              void* d_out, int out_size)
{
    const float* x      = (const float*)d_in[0];
    const int*   eidx   = (const int*)  d_in[1];
    const float* ea     = (const float*)d_in[2];
    const float* lin1_w = (const float*)d_in[3];
    const float* lin1_b = (const float*)d_in[4];
    const float* cls_w1 = (const float*)d_in[23];
    const float* cls_b1 = (const float*)d_in[24];
    const float* cls_w2 = (const float*)d_in[25];
    const float* cls_b2 = (const float*)d_in[26];

    const int NN = in_sizes[0] / 64;
    const int E  = in_sizes[2] / 32;
    const int* src = eidx;
    const int* dst = eidx + E;

    float *h, *agg, *hid, *eas;
    int *srcs, *dsts, *deg, *off, *cur, *perm;
    cudaGetSymbolAddress((void**)&h,    g_h);
    cudaGetSymbolAddress((void**)&agg,  g_agg);
    cudaGetSymbolAddress((void**)&hid,  g_hid);
    cudaGetSymbolAddress((void**)&eas,  g_eas);
    cudaGetSymbolAddress((void**)&srcs, g_srcs);
    cudaGetSymbolAddress((void**)&dsts, g_dsts);
    cudaGetSymbolAddress((void**)&deg,  g_deg);
    cudaGetSymbolAddress((void**)&off,  g_off);
    cudaGetSymbolAddress((void**)&cur,  g_cur);
    cudaGetSymbolAddress((void**)&perm, g_perm);

    static bool attr_set = false;
    if (!attr_set) {
        cudaFuncSetAttribute(cls_tc_kernel,
                             cudaFuncAttributeMaxDynamicSharedMemorySize, CLS_SMEM);
        attr_set = true;
    }

    const dim3 gnode(1, (unsigned)((NN + BM - 1) / BM));
    const int eblocks = (E + SE - 1) / SE;
    const int pblocks = (E + 31) / 32;
    const int copy_n4 = (NN * HID) / 4;
    const int copy_blocks = (copy_n4 + 255) / 256;

    // ---- CSR build + sorted-edge materialization (once) ----
    zero_int_kernel<<<(NN + 255) / 256, 256>>>(deg, NN);
    hist_kernel<<<(E + 255) / 256, 256>>>(dst, deg, E);
    scan_kernel<<<1, 1024>>>(deg, off, cur, NN);
    fill_kernel<<<(E + 255) / 256, 256>>>(dst, cur, perm, E);
    permute_kernel<<<pblocks, 128>>>(perm, src, dst, ea, eas, srcs, dsts, E);

    tgemm_kernel<false><<<gnode, 256>>>(x, 64, lin1_w, HID, lin1_b, h, HID, NN, 64);

    for (int c = 0; c < 3; c++) {
        const float* ew = (const float*)d_in[5 + 6 * c];
        const float* eb = (const float*)d_in[6 + 6 * c];
        const float* w1 = (const float*)d_in[7 + 6 * c];
        const float* b1 = (const float*)d_in[8 + 6 * c];
        const float* w2 = (const float*)d_in[9 + 6 * c];
        const float* b2 = (const float*)d_in[10 + 6 * c];

        copy_kernel<<<copy_blocks, 256>>>((float4*)agg, (const float4*)h, copy_n4);
        edge_scatter_tc<<<eblocks, 256>>>(h, srcs, dsts, eas, ew, eb, agg, E);
        tgemm_kernel<true><<<gnode, 256>>>(agg, HID, w1, HID, b1, hid, HID, NN, HID);
        tgemm_kernel<true><<<gnode, 256>>>(hid, HID, w2, HID, b2, h, HID, NN, HID);
    }

    tgemm_kernel<false><<<gnode, 256>>>(h, HID, cls_w1, HID, nullptr, hid, HID, NN, HID);
    tgemm_kernel<false><<<gnode, 256>>>(h, HID, cls_w1 + 128 * HID, HID, nullptr, agg, HID, NN, HID);

    cls_tc_kernel<<<eblocks, 256, CLS_SMEM>>>(hid, agg, src, dst, ea,
                                              cls_w1 + 256 * HID, cls_b1,
                                              cls_w2, cls_b2, (float*)d_out, E);
}